// round 2
// baseline (speedup 1.0000x reference)
#include <cuda_runtime.h>

// SNN: B=4096, T=256, I=7, H=64, O=8
// d_in: [0]=x (B,T,I) f32, [1]=hidden_states (B,1,H) f32, [2]=W1 (H,I),
//       [3]=b1 (H,), [4]=W2 (O,H), [5]=b2 (O,)
// d_out: outputs (B,T,O) f32 followed by new_hidden (B,T,H) f32.

#define BETA 0.8f
#define THRESH 1.0f

constexpr int T_ = 256;
constexpr int I_ = 7;
constexpr int H_ = 64;
constexpr int O_ = 8;
constexpr int WARPS_PER_BLOCK = 4;
constexpr int TCHUNK = 64;

__global__ __launch_bounds__(WARPS_PER_BLOCK * 32)
void snn_kernel(const float* __restrict__ x,
                const float* __restrict__ hs,
                const float* __restrict__ W1,
                const float* __restrict__ b1,
                const float* __restrict__ W2,
                const float* __restrict__ b2,
                float* __restrict__ out,     // (B,T,8)
                float* __restrict__ newh,    // (B,T,64)
                int B)
{
    __shared__ float xs[WARPS_PER_BLOCK][TCHUNK * I_];

    const int w    = threadIdx.x >> 5;
    const int lane = threadIdx.x & 31;
    const int b    = blockIdx.x * WARPS_PER_BLOCK + w;
    if (b >= B) return;

    const int h0 = 2 * lane;
    const int h1 = 2 * lane + 1;

    // Per-lane weights (resident in registers)
    float w1a[I_], w1b[I_];
#pragma unroll
    for (int i = 0; i < I_; i++) {
        w1a[i] = W1[h0 * I_ + i];
        w1b[i] = W1[h1 * I_ + i];
    }
    const float b1a = b1[h0];
    const float b1b = b1[h1];

    float w2a[O_], w2b[O_];
#pragma unroll
    for (int o = 0; o < O_; o++) {
        w2a[o] = W2[o * H_ + h0];
        w2b[o] = W2[o * H_ + h1];
    }
    const float bias2 = b2[lane & 7];

    float mem0 = hs[(size_t)b * H_ + h0];
    float mem1 = hs[(size_t)b * H_ + h1];

    const float* xb = x    + (size_t)b * T_ * I_;
    float*       nh = newh + (size_t)b * T_ * H_;
    float*       ob = out  + (size_t)b * T_ * O_;

    for (int c0 = 0; c0 < T_; c0 += TCHUNK) {
        // Stage x chunk for this batch into shared (coalesced float4 loads).
        // TCHUNK*I_ = 448 floats = 112 float4; offsets are 16B-aligned.
        {
            const float4* src = (const float4*)(xb + c0 * I_);
            float4*       dst = (float4*)xs[w];
#pragma unroll
            for (int i = 0; i < (TCHUNK * I_ / 4 + 31) / 32; i++) {
                int idx = lane + i * 32;
                if (idx < TCHUNK * I_ / 4) dst[idx] = src[idx];
            }
        }
        __syncwarp();

#pragma unroll 4
        for (int tt = 0; tt < TCHUNK; tt++) {
            const int t = c0 + tt;
            const float* xr = &xs[w][tt * I_];

            // cur1 = x @ W1^T + b1 for this lane's two hidden units
            float cur0 = b1a, cur1 = b1b;
#pragma unroll
            for (int i = 0; i < I_; i++) {
                const float xv = xr[i];   // broadcast LDS, conflict-free
                cur0 = fmaf(xv, w1a[i], cur0);
                cur1 = fmaf(xv, w1b[i], cur1);
            }

            // reset spike on previous mem, then leaky integrate
            const float r0 = (mem0 > THRESH) ? THRESH : 0.0f;
            const float r1 = (mem1 > THRESH) ? THRESH : 0.0f;
            mem0 = fmaf(BETA, mem0, cur0) - r0;
            mem1 = fmaf(BETA, mem1, cur1) - r1;

            // record post-update membrane (coalesced STG.64 across warp)
            *reinterpret_cast<float2*>(nh + t * H_ + 2 * lane) =
                make_float2(mem0, mem1);

            // output spikes
            const float s0 = (mem0 > THRESH) ? 1.0f : 0.0f;
            const float s1 = (mem1 > THRESH) ? 1.0f : 0.0f;

            // per-lane partial of outputs: p[o] = s0*W2[o,h0] + s1*W2[o,h1]
            float p[O_];
#pragma unroll
            for (int o = 0; o < O_; o++)
                p[o] = fmaf(s0, w2a[o], s1 * w2b[o]);

            // Fold 8 values across 32 lanes: after steps xor 4,2,1 each lane
            // holds the partial for value index (lane & 7); then butterfly
            // xor 8,16 sums the 4 replicas.
            {
                const bool hi = (lane & 4) != 0;
                float t0 = hi ? p[0] : p[4];
                float t1 = hi ? p[1] : p[5];
                float t2 = hi ? p[2] : p[6];
                float t3 = hi ? p[3] : p[7];
                t0 = __shfl_xor_sync(0xFFFFFFFFu, t0, 4);
                t1 = __shfl_xor_sync(0xFFFFFFFFu, t1, 4);
                t2 = __shfl_xor_sync(0xFFFFFFFFu, t2, 4);
                t3 = __shfl_xor_sync(0xFFFFFFFFu, t3, 4);
                p[0] = (hi ? p[4] : p[0]) + t0;
                p[1] = (hi ? p[5] : p[1]) + t1;
                p[2] = (hi ? p[6] : p[2]) + t2;
                p[3] = (hi ? p[7] : p[3]) + t3;
            }
            {
                const bool hi = (lane & 2) != 0;
                float t0 = hi ? p[0] : p[2];
                float t1 = hi ? p[1] : p[3];
                t0 = __shfl_xor_sync(0xFFFFFFFFu, t0, 2);
                t1 = __shfl_xor_sync(0xFFFFFFFFu, t1, 2);
                p[0] = (hi ? p[2] : p[0]) + t0;
                p[1] = (hi ? p[3] : p[1]) + t1;
            }
            {
                const bool hi = (lane & 1) != 0;
                float t0 = hi ? p[0] : p[1];
                t0 = __shfl_xor_sync(0xFFFFFFFFu, t0, 1);
                p[0] = (hi ? p[1] : p[0]) + t0;
            }
            p[0] += __shfl_xor_sync(0xFFFFFFFFu, p[0], 8);
            p[0] += __shfl_xor_sync(0xFFFFFFFFu, p[0], 16);

            if (lane < O_) ob[t * O_ + lane] = p[0] + bias2;
        }
        __syncwarp();
    }
}

extern "C" void kernel_launch(void* const* d_in, const int* in_sizes, int n_in,
                              void* d_out, int out_size)
{
    const float* x  = (const float*)d_in[0];
    const float* hs = (const float*)d_in[1];
    const float* W1 = (const float*)d_in[2];
    const float* b1 = (const float*)d_in[3];
    const float* W2 = (const float*)d_in[4];
    const float* b2 = (const float*)d_in[5];

    // B from hidden_states size (B*1*H)
    const int B = in_sizes[1] / H_;

    float* out  = (float*)d_out;                       // (B,T,O)
    float* newh = (float*)d_out + (size_t)B * T_ * O_; // (B,T,H)

    const int blocks = (B + WARPS_PER_BLOCK - 1) / WARPS_PER_BLOCK;
    snn_kernel<<<blocks, WARPS_PER_BLOCK * 32>>>(x, hs, W1, b1, W2, b2,
                                                 out, newh, B);
}